// round 11
// baseline (speedup 1.0000x reference)
#include <cuda_runtime.h>
#include <cuda_fp16.h>
#include <cstdint>

#define BQ    4
#define NSEQ  200000
#define EDIM  128
#define NIDX  2048
#define ROWS  (BQ * NSEQ)            /* 800000 */
#define NTILES (ROWS / 128)          /* 6250 exact */
#define OUT_ELEMS (BQ * NIDX * EDIM) /* 1048576 */
#define ATTN_OFF  OUT_ELEMS
#define NSEG (BQ * NIDX)             /* 8192 */

// ---------------- device scratch (no cudaMalloc allowed) ----------------
__device__ float    g_imp[ROWS];        // exp(importance)  (0 for masked rows)
__device__ float    g_segsum[NSEG];
__device__ uint32_t g_Wfrag[8192];      // W as fragment-ordered fp16x2 pairs (32 KB)
__device__ unsigned g_tilectr;          // work-stealing tile counter

// ---------------- helpers ----------------
__device__ __forceinline__ uint32_t smem_u32(const void* p) {
    uint32_t a;
    asm("{ .reg .u64 t; cvta.to.shared.u64 t, %1; cvt.u32.u64 %0, t; }" : "=r"(a) : "l"(p));
    return a;
}
// pack two f32 -> f16x2 (lo = first arg)
__device__ __forceinline__ uint32_t f16x2_pack(float lo, float hi) {
    uint32_t r;
    asm("cvt.rn.f16x2.f32 %0, %1, %2;" : "=r"(r) : "f"(hi), "f"(lo));
    return r;
}
__device__ __forceinline__ float tanh_approx(float f) {
    float r;
    asm("tanh.approx.f32 %0, %1;" : "=f"(r) : "f"(f));
    return r;
}
__device__ __forceinline__ void cp_async16(uint32_t dst, const void* src) {
    asm volatile("cp.async.cg.shared.global [%0], [%1], 16;" :: "r"(dst), "l"(src));
}
#define CP_COMMIT()  asm volatile("cp.async.commit_group;" ::: "memory")
#define CP_WAIT(N)   asm volatile("cp.async.wait_group %0;" :: "n"(N) : "memory")

#define LDS128(r0_, r1_, r2_, r3_, addr) \
    asm volatile("ld.shared.v4.u32 {%0,%1,%2,%3}, [%4];" \
        : "=r"(r0_), "=r"(r1_), "=r"(r2_), "=r"(r3_) : "r"(addr))

#define LDSM_X4(r0_, r1_, r2_, r3_, addr) \
    asm volatile("ldmatrix.sync.aligned.m8n8.x4.shared.b16 {%0,%1,%2,%3}, [%4];" \
        : "=r"(r0_), "=r"(r1_), "=r"(r2_), "=r"(r3_) : "r"(addr))

#define MMA_F16(d, a0, a1, a2, a3, b0, b1) \
    asm volatile("mma.sync.aligned.m16n8k16.row.col.f32.f16.f16.f32 " \
        "{%0,%1,%2,%3}, {%4,%5,%6,%7}, {%8,%9}, {%0,%1,%2,%3};" \
        : "+f"((d)[0]), "+f"((d)[1]), "+f"((d)[2]), "+f"((d)[3]) \
        : "r"(a0), "r"(a1), "r"(a2), "r"(a3), "r"(b0), "r"(b1))

#define REDV4(dst, a, b, c, dd) \
    asm volatile("red.global.add.v4.f32 [%0], {%1, %2, %3, %4};" \
        :: "l"(dst), "f"(a), "f"(b), "f"(c), "f"(dd) : "memory")

// ---------------- SMEM layout (K1) ----------------
// f16 X tile: 128 rows x 136 f16 (272 B stride) -> conflict-free ldmatrix.
// W frags:    [wc(2)][step(8)][lane(32)] x 64B payload padded to 80 B/lane.
#define ROWH_B    272
#define XF16_PB   (128 * ROWH_B)      /* 34816 */
#define SM_B      0                   /* 512B bias   */
#define SM_CTX    512                 /* 512B ctx    */
#define SM_PACC   1024                /* 1024B       */
#define SM_T      2048                /* 16B tile broadcast */
#define SM_E      2176                /* 512B: e per row      */
#define SM_SEG    2688                /* 512B: segg per row   */
#define SM_WF     3200                /* 40960B W fragments */
#define SM_XF16   (SM_WF + 40960)     /* 44160 */
#define SMEM_TOTAL (SM_XF16 + XF16_PB) /* 78976 */

// =========================== K0: init + W fragment pack ===========================
__global__ void k0_init(float* out, const float* __restrict__ W) {
    int i = blockIdx.x * blockDim.x + threadIdx.x;
    if (i < OUT_ELEMS) out[i] = 0.0f;
    if (i < NSEG) g_segsum[i] = 0.0f;
    if (i < 8192) {
        int h  = i & 1;          // k-half (+8)
        int nb = (i >> 1) & 7;   // n8 block within warp's 64 cols
        int ln = (i >> 4) & 31;  // lane
        int st = (i >> 9) & 7;   // k16 step
        int wc = i >> 12;        // warp_c
        int r0 = ln >> 2, c0 = ln & 3;
        int n = 64 * wc + 8 * nb + r0;
        int k = 16 * st + 2 * c0 + 8 * h;
        uint32_t p = f16x2_pack(W[n * 128 + k], W[n * 128 + k + 1]);
        g_Wfrag[((wc * 8 + st) * 32 + ln) * 16 + nb * 2 + h] = p;
    }
    if (i == 0) g_tilectr = 0u;
}

// ============ K1: persistent fp16 GEMM + tanh + exp + segsum + fused scatter ============
// out[seg] accumulates x*e (unnormalized); K4 divides by segsum afterwards.
// x for the scatter comes from the f16 smem tile (already resident) - no gmem re-read.
__global__ __launch_bounds__(256, 1)
void k1_importance(const float* __restrict__ x,
                   const float* __restrict__ bv, const float* __restrict__ ctx,
                   const int* __restrict__ mask, const int* __restrict__ index,
                   float* __restrict__ out) {
    extern __shared__ char smem[];
    uint32_t sbase = smem_u32(smem);
    int tid = threadIdx.x;
    int l = tid & 31, wid = tid >> 5;
    int warp_r = wid & 3;        // rows 32*warp_r .. +31
    int warp_c = wid >> 2;       // cols 64*warp_c .. +63
    int r0 = l >> 2, c0 = l & 3;
    int* smt = (int*)(smem + SM_T);

    if (tid < 128) {
        ((float*)(smem + SM_B))[tid]   = bv[tid];
        ((float*)(smem + SM_CTX))[tid] = ctx[tid];
    }
    if (tid == 0) smt[0] = (int)atomicAdd(&g_tilectr, 1u);
    __syncthreads();
    int t = smt[0];
    if (t >= NTILES) return;     // late CTA under work stealing (uniform per CTA)

    // copy W fragments into padded smem (2048 x 16B)
#pragma unroll
    for (int i = 0; i < 8; i++) {
        int c = i * 256 + tid;
        int grp = c >> 2, off = c & 3;
        cp_async16(sbase + SM_WF + grp * 80 + off * 16, (const char*)g_Wfrag + c * 16);
    }
    CP_COMMIT();

    // prefetch first x tile into registers
    const float4* xb = (const float4*)x;
    float4 xr[16];
#pragma unroll
    for (int i = 0; i < 16; i++)
        xr[i] = __ldg(xb + (size_t)t * 4096 + i * 256 + tid);

    CP_WAIT(0);   // own W chunks done; cross-thread visibility via in-loop sync

    // per-lane bases
    const uint32_t a_sm = sbase + SM_XF16
                        + (uint32_t)(32 * warp_r + (l & 15)) * ROWH_B + ((l >> 4) << 4);
    const uint32_t wf_base = sbase + SM_WF + (uint32_t)((warp_c * 8) * 32 + l) * 80;
    const float* sb = (const float*)(smem + SM_B);
    const float* sc = (const float*)(smem + SM_CTX);
    float* pacc = (float*)(smem + SM_PACC);
    float* se   = (float*)(smem + SM_E);
    int*   ssg  = (int*)(smem + SM_SEG);
    char* Hp = smem + SM_XF16;

    for (;;) {
        // ---- convert + store current tile's x (from regs) into shared f16 ----
#pragma unroll
        for (int i = 0; i < 16; i++) {
            int c = i * 256 + tid;
            int row = c >> 5, u = c & 31;
            uint2 p;
            p.x = f16x2_pack(xr[i].x, xr[i].y);
            p.y = f16x2_pack(xr[i].z, xr[i].w);
            *(uint2*)(Hp + row * ROWH_B + u * 8) = p;
        }
        if (tid == 0) smt[0] = (int)atomicAdd(&g_tilectr, 1u);
        __syncthreads();                       // STS visible; smt visible; W visible (1st iter)
        int tn = smt[0];
        bool pend = (tn < NTILES);
        if (pend) {                            // prefetch next tile; hidden under MMA loop
#pragma unroll
            for (int i = 0; i < 16; i++)
                xr[i] = __ldg(xb + (size_t)tn * 4096 + i * 256 + tid);
        }

        float d[2][8][4];
#pragma unroll
        for (int mb = 0; mb < 2; mb++)
#pragma unroll
            for (int nb = 0; nb < 8; nb++)
#pragma unroll
                for (int r = 0; r < 4; r++) d[mb][nb][r] = 0.0f;

#pragma unroll
        for (int st = 0; st < 8; st++) {       // 8 k16 steps (32B each along row)
            uint32_t A[2][4];
            LDSM_X4(A[0][0], A[0][1], A[0][2], A[0][3], a_sm + st * 32);
            LDSM_X4(A[1][0], A[1][1], A[1][2], A[1][3], a_sm + st * 32 + 16 * ROWH_B);
            uint32_t Bv[4][4];
            uint32_t ba = wf_base + (uint32_t)(st * 32) * 80;
#pragma unroll
            for (int q = 0; q < 4; q++)
                LDS128(Bv[q][0], Bv[q][1], Bv[q][2], Bv[q][3], ba + q * 16);
#pragma unroll
            for (int nb = 0; nb < 8; nb++) {
                uint32_t bb0 = Bv[nb >> 1][(nb & 1) * 2];
                uint32_t bb1 = Bv[nb >> 1][(nb & 1) * 2 + 1];
                MMA_F16(d[0][nb], A[0][0], A[0][1], A[0][2], A[0][3], bb0, bb1);
                MMA_F16(d[1][nb], A[1][0], A[1][1], A[1][2], A[1][3], bb0, bb1);
            }
        }

        // ---- epilogue: tanh.approx + ctx-dot on fragments ----
        float acc[4] = {0.f, 0.f, 0.f, 0.f};   // [mb*2 + hi8]
#pragma unroll
        for (int mb = 0; mb < 2; mb++) {
#pragma unroll
            for (int nb = 0; nb < 8; nb++) {
                int cb = 64 * warp_c + nb * 8 + c0 * 2;
#pragma unroll
                for (int r = 0; r < 4; r++) {
                    int c = cb + (r & 1);
                    float th = tanh_approx(d[mb][nb][r] + sb[c]);
                    acc[mb * 2 + (r >> 1)] = fmaf(sc[c], th, acc[mb * 2 + (r >> 1)]);
                }
            }
        }
#pragma unroll
        for (int s = 0; s < 4; s++) {
            acc[s] += __shfl_xor_sync(0xFFFFFFFFu, acc[s], 1);
            acc[s] += __shfl_xor_sync(0xFFFFFFFFu, acc[s], 2);
        }
        if (c0 == 0) {
#pragma unroll
            for (int s = 0; s < 4; s++) {
                int row = 32 * warp_r + 16 * (s >> 1) + 8 * (s & 1) + r0;
                pacc[row * 2 + warp_c] = acc[s];
            }
        }
        __syncthreads();   // pacc ready

        if (tid < 128) {
            float impv = (pacc[tid * 2] + pacc[tid * 2 + 1]) * 0.08838834764831843f;
            int row = t * 128 + tid;
            float e = 0.0f;
            int segg = 0;
            if (mask[row] != 0) {
                e = __expf(impv);              // |impv| <= ~9: no overflow possible
                int seg = index[row];
                int bq = row / NSEQ;
                segg = bq * NIDX + seg;
                atomicAdd(&g_segsum[segg], e);
            }
            g_imp[row] = e;
            se[tid] = e;
            ssg[tid] = segg;
        }
        __syncthreads();   // se/ssg visible to all warps

        // ---- fused scatter: out[seg] += x_f16 * e (x from resident smem tile) ----
        {
            int row = tid & 127;
            int h = tid >> 7;                  // which half of the 128-col row
            float e = se[row];
            if (e != 0.0f) {
                int segg = ssg[row];
                float* dst = out + ((size_t)segg << 7) + h * 64;
                const __half2* src = (const __half2*)(Hp + row * ROWH_B + h * 128);
#pragma unroll
                for (int u = 0; u < 16; u++) {
                    float2 f0 = __half22float2(src[u * 2]);
                    float2 f1 = __half22float2(src[u * 2 + 1]);
                    REDV4(dst + u * 4, f0.x * e, f0.y * e, f1.x * e, f1.y * e);
                }
            }
        }
        __syncthreads();   // Hp reads done before next iteration's STS

        if (!pend) break;
        t = tn;
    }
}

// ============ K4: normalize out by segsum + emit attn weights ============
__global__ __launch_bounds__(256)
void k4_norm(const int* __restrict__ index, float* __restrict__ out) {
    int i = blockIdx.x * blockDim.x + threadIdx.x;
    if (i < OUT_ELEMS) {
        float s = g_segsum[i >> 7];
        float v = out[i];
        out[i] = (s > 0.0f) ? v / s : 0.0f;
    }
    if (i < ROWS) {
        float e = g_imp[i];
        float a = 0.0f;
        if (e != 0.0f) {
            int seg = index[i];
            int bq = i / NSEQ;
            a = e / g_segsum[bq * NIDX + seg];
        }
        out[ATTN_OFF + i] = a;
    }
}

// ============================ launch ============================
extern "C" void kernel_launch(void* const* d_in, const int* in_sizes, int n_in,
                              void* d_out, int out_size) {
    const float* x     = (const float*)d_in[0];
    const float* W     = (const float*)d_in[1];
    const float* bv    = (const float*)d_in[2];
    const float* ctx   = (const float*)d_in[3];
    const int*   mask  = (const int*)d_in[4];
    const int*   index = (const int*)d_in[5];
    float* out = (float*)d_out;

    cudaFuncSetAttribute(k1_importance, cudaFuncAttributeMaxDynamicSharedMemorySize, SMEM_TOTAL);

    k0_init<<<(OUT_ELEMS + 255) / 256, 256>>>(out, W);
    k1_importance<<<152, 256, SMEM_TOTAL>>>(x, bv, ctx, mask, index, out);
    k4_norm<<<(OUT_ELEMS + 255) / 256, 256>>>(index, out);
}

// round 12
// speedup vs baseline: 1.0077x; 1.0077x over previous
#include <cuda_runtime.h>
#include <cuda_fp16.h>
#include <cstdint>

#define BQ    4
#define NSEQ  200000
#define EDIM  128
#define NIDX  2048
#define ROWS  (BQ * NSEQ)            /* 800000 */
#define NTILES (ROWS / 128)          /* 6250 exact */
#define OUT_ELEMS (BQ * NIDX * EDIM) /* 1048576 */
#define ATTN_OFF  OUT_ELEMS
#define NSEG (BQ * NIDX)             /* 8192 */

// ---------------- device scratch (no cudaMalloc allowed) ----------------
__device__ float    g_imp[ROWS];        // exp(importance)  (0 for masked rows)
__device__ float    g_segsum[NSEG];
__device__ uint32_t g_Wfrag[8192];      // W as fragment-ordered fp16x2 pairs (32 KB)
__device__ unsigned g_tilectr;          // work-stealing tile counter
__device__ uint2    g_xf16[(size_t)ROWS * 32];  // x in f16 (204.8 MB sidecar)

// ---------------- helpers ----------------
__device__ __forceinline__ uint32_t smem_u32(const void* p) {
    uint32_t a;
    asm("{ .reg .u64 t; cvta.to.shared.u64 t, %1; cvt.u32.u64 %0, t; }" : "=r"(a) : "l"(p));
    return a;
}
// pack two f32 -> f16x2 (lo = first arg)
__device__ __forceinline__ uint32_t f16x2_pack(float lo, float hi) {
    uint32_t r;
    asm("cvt.rn.f16x2.f32 %0, %1, %2;" : "=r"(r) : "f"(hi), "f"(lo));
    return r;
}
__device__ __forceinline__ float tanh_approx(float f) {
    float r;
    asm("tanh.approx.f32 %0, %1;" : "=f"(r) : "f"(f));
    return r;
}
__device__ __forceinline__ void cp_async16(uint32_t dst, const void* src) {
    asm volatile("cp.async.cg.shared.global [%0], [%1], 16;" :: "r"(dst), "l"(src));
}
#define CP_COMMIT()  asm volatile("cp.async.commit_group;" ::: "memory")
#define CP_WAIT(N)   asm volatile("cp.async.wait_group %0;" :: "n"(N) : "memory")

#define LDS128(r0_, r1_, r2_, r3_, addr) \
    asm volatile("ld.shared.v4.u32 {%0,%1,%2,%3}, [%4];" \
        : "=r"(r0_), "=r"(r1_), "=r"(r2_), "=r"(r3_) : "r"(addr))

#define LDSM_X4(r0_, r1_, r2_, r3_, addr) \
    asm volatile("ldmatrix.sync.aligned.m8n8.x4.shared.b16 {%0,%1,%2,%3}, [%4];" \
        : "=r"(r0_), "=r"(r1_), "=r"(r2_), "=r"(r3_) : "r"(addr))

#define MMA_F16(d, a0, a1, a2, a3, b0, b1) \
    asm volatile("mma.sync.aligned.m16n8k16.row.col.f32.f16.f16.f32 " \
        "{%0,%1,%2,%3}, {%4,%5,%6,%7}, {%8,%9}, {%0,%1,%2,%3};" \
        : "+f"((d)[0]), "+f"((d)[1]), "+f"((d)[2]), "+f"((d)[3]) \
        : "r"(a0), "r"(a1), "r"(a2), "r"(a3), "r"(b0), "r"(b1))

#define REDV4(dst, a, b, c, dd) \
    asm volatile("red.global.add.v4.f32 [%0], {%1, %2, %3, %4};" \
        :: "l"(dst), "f"(a), "f"(b), "f"(c), "f"(dd) : "memory")

// ---------------- SMEM layout (K1) ----------------
// f16 X tile: 128 rows x 136 f16 (272 B stride) -> conflict-free ldmatrix.
// W frags:    [wc(2)][step(8)][lane(32)] x 64B payload padded to 80 B/lane.
#define ROWH_B    272
#define XF16_PB   (128 * ROWH_B)      /* 34816 */
#define SM_B      0                   /* 512B bias   */
#define SM_CTX    512                 /* 512B ctx    */
#define SM_PACC   1024                /* 1024B       */
#define SM_T      2048                /* 16B tile broadcast */
#define SM_WF     2176                /* 40960B W fragments */
#define SM_XF16   (SM_WF + 40960)     /* 43136 */
#define SMEM_TOTAL (SM_XF16 + XF16_PB) /* 77952 */

// =========================== K0: init + W fragment pack ===========================
__global__ void k0_init(float* out, const float* __restrict__ W) {
    int i = blockIdx.x * blockDim.x + threadIdx.x;
    if (i < OUT_ELEMS) out[i] = 0.0f;
    if (i < NSEG) g_segsum[i] = 0.0f;
    if (i < 8192) {
        int h  = i & 1;          // k-half (+8)
        int nb = (i >> 1) & 7;   // n8 block within warp's 64 cols
        int ln = (i >> 4) & 31;  // lane
        int st = (i >> 9) & 7;   // k16 step
        int wc = i >> 12;        // warp_c
        int r0 = ln >> 2, c0 = ln & 3;
        int n = 64 * wc + 8 * nb + r0;
        int k = 16 * st + 2 * c0 + 8 * h;
        uint32_t p = f16x2_pack(W[n * 128 + k], W[n * 128 + k + 1]);
        g_Wfrag[((wc * 8 + st) * 32 + ln) * 16 + nb * 2 + h] = p;
    }
    if (i == 0) g_tilectr = 0u;
}

// ============ K1: persistent fp16 GEMM + tanh + exp + segsum (+ f16 x sidecar) ============
// No max-subtraction: importance is bounded (|imp| <= ~9); masked rows -> exp(-1e9) == 0.
// The convert phase also streams the packed f16 x to gmem so K3 reads half the bytes.
__global__ __launch_bounds__(256, 1)
void k1_importance(const float* __restrict__ x,
                   const float* __restrict__ bv, const float* __restrict__ ctx,
                   const int* __restrict__ mask, const int* __restrict__ index) {
    extern __shared__ char smem[];
    uint32_t sbase = smem_u32(smem);
    int tid = threadIdx.x;
    int l = tid & 31, wid = tid >> 5;
    int warp_r = wid & 3;        // rows 32*warp_r .. +31
    int warp_c = wid >> 2;       // cols 64*warp_c .. +63
    int r0 = l >> 2, c0 = l & 3;
    int* smt = (int*)(smem + SM_T);

    if (tid < 128) {
        ((float*)(smem + SM_B))[tid]   = bv[tid];
        ((float*)(smem + SM_CTX))[tid] = ctx[tid];
    }
    if (tid == 0) smt[0] = (int)atomicAdd(&g_tilectr, 1u);
    __syncthreads();
    int t = smt[0];
    if (t >= NTILES) return;     // late CTA under work stealing (uniform per CTA)

    // copy W fragments into padded smem (2048 x 16B)
#pragma unroll
    for (int i = 0; i < 8; i++) {
        int c = i * 256 + tid;
        int grp = c >> 2, off = c & 3;
        cp_async16(sbase + SM_WF + grp * 80 + off * 16, (const char*)g_Wfrag + c * 16);
    }
    CP_COMMIT();

    // prefetch first x tile into registers
    const float4* xb = (const float4*)x;
    float4 xr[16];
#pragma unroll
    for (int i = 0; i < 16; i++)
        xr[i] = __ldg(xb + (size_t)t * 4096 + i * 256 + tid);

    CP_WAIT(0);   // own W chunks done; cross-thread visibility via in-loop sync

    // per-lane bases
    const uint32_t a_sm = sbase + SM_XF16
                        + (uint32_t)(32 * warp_r + (l & 15)) * ROWH_B + ((l >> 4) << 4);
    const uint32_t wf_base = sbase + SM_WF + (uint32_t)((warp_c * 8) * 32 + l) * 80;
    const float* sb = (const float*)(smem + SM_B);
    const float* sc = (const float*)(smem + SM_CTX);
    float* pacc = (float*)(smem + SM_PACC);
    char* Hp = smem + SM_XF16;

    for (;;) {
        // ---- convert: regs -> shared f16 tile AND gmem f16 sidecar ----
#pragma unroll
        for (int i = 0; i < 16; i++) {
            int c = i * 256 + tid;
            int row = c >> 5, u = c & 31;
            uint2 p;
            p.x = f16x2_pack(xr[i].x, xr[i].y);
            p.y = f16x2_pack(xr[i].z, xr[i].w);
            *(uint2*)(Hp + row * ROWH_B + u * 8) = p;
            g_xf16[(size_t)t * 4096 + c] = p;     // coalesced STG.64, off critical path
        }
        if (tid == 0) smt[0] = (int)atomicAdd(&g_tilectr, 1u);
        __syncthreads();                       // STS visible; smt visible; W visible (1st iter)
        int tn = smt[0];
        bool pend = (tn < NTILES);
        if (pend) {                            // prefetch next tile; hidden under MMA loop
#pragma unroll
            for (int i = 0; i < 16; i++)
                xr[i] = __ldg(xb + (size_t)tn * 4096 + i * 256 + tid);
        }

        float d[2][8][4];
#pragma unroll
        for (int mb = 0; mb < 2; mb++)
#pragma unroll
            for (int nb = 0; nb < 8; nb++)
#pragma unroll
                for (int r = 0; r < 4; r++) d[mb][nb][r] = 0.0f;

#pragma unroll
        for (int st = 0; st < 8; st++) {       // 8 k16 steps (32B each along row)
            uint32_t A[2][4];
            LDSM_X4(A[0][0], A[0][1], A[0][2], A[0][3], a_sm + st * 32);
            LDSM_X4(A[1][0], A[1][1], A[1][2], A[1][3], a_sm + st * 32 + 16 * ROWH_B);
            uint32_t Bv[4][4];
            uint32_t ba = wf_base + (uint32_t)(st * 32) * 80;
#pragma unroll
            for (int q = 0; q < 4; q++)
                LDS128(Bv[q][0], Bv[q][1], Bv[q][2], Bv[q][3], ba + q * 16);
#pragma unroll
            for (int nb = 0; nb < 8; nb++) {
                uint32_t bb0 = Bv[nb >> 1][(nb & 1) * 2];
                uint32_t bb1 = Bv[nb >> 1][(nb & 1) * 2 + 1];
                MMA_F16(d[0][nb], A[0][0], A[0][1], A[0][2], A[0][3], bb0, bb1);
                MMA_F16(d[1][nb], A[1][0], A[1][1], A[1][2], A[1][3], bb0, bb1);
            }
        }

        // ---- epilogue: tanh.approx + ctx-dot on fragments ----
        float acc[4] = {0.f, 0.f, 0.f, 0.f};   // [mb*2 + hi8]
#pragma unroll
        for (int mb = 0; mb < 2; mb++) {
#pragma unroll
            for (int nb = 0; nb < 8; nb++) {
                int cb = 64 * warp_c + nb * 8 + c0 * 2;
#pragma unroll
                for (int r = 0; r < 4; r++) {
                    int c = cb + (r & 1);
                    float th = tanh_approx(d[mb][nb][r] + sb[c]);
                    acc[mb * 2 + (r >> 1)] = fmaf(sc[c], th, acc[mb * 2 + (r >> 1)]);
                }
            }
        }
#pragma unroll
        for (int s = 0; s < 4; s++) {
            acc[s] += __shfl_xor_sync(0xFFFFFFFFu, acc[s], 1);
            acc[s] += __shfl_xor_sync(0xFFFFFFFFu, acc[s], 2);
        }
        if (c0 == 0) {
#pragma unroll
            for (int s = 0; s < 4; s++) {
                int row = 32 * warp_r + 16 * (s >> 1) + 8 * (s & 1) + r0;
                pacc[row * 2 + warp_c] = acc[s];
            }
        }
        __syncthreads();   // pacc ready; also: all Xf16 reads done before next STS

        if (tid < 128) {
            float impv = (pacc[tid * 2] + pacc[tid * 2 + 1]) * 0.08838834764831843f;
            int row = t * 128 + tid;
            float e = 0.0f;
            if (mask[row] != 0) {
                e = __expf(impv);              // |impv| <= ~9: no overflow possible
                int seg = index[row];
                int bq = row / NSEQ;
                atomicAdd(&g_segsum[bq * NIDX + seg], e);
            }
            g_imp[row] = e;
        }

        if (!pend) break;
        t = tn;
    }
}

// ============ K3: weights + scatter-add of f16 x (32 rows/warp, 4-way unrolled) ============
__global__ __launch_bounds__(256)
void k3_scatter(const int* __restrict__ index, float* __restrict__ out) {
    int warp = (blockIdx.x << 3) + (threadIdx.x >> 5);   // 25000 warps
    int lane = threadIdx.x & 31;
    int rbase = warp * 32;                               // NSEQ % 32 == 0: no bq straddle
    int row = rbase + lane;

    float e  = g_imp[row];
    int seg  = index[row];
    int bq   = row / NSEQ;
    int segg = bq * NIDX + seg;
    float s  = g_segsum[segg];
    float w  = (e != 0.0f) ? e / s : 0.0f;
    out[ATTN_OFF + row] = w;

    unsigned act = __ballot_sync(0xFFFFFFFFu, w != 0.0f);
    while (act) {
        int i0 = __ffs(act) - 1;             act &= (act - 1);
        int i1 = act ? __ffs(act) - 1 : -1;  if (i1 >= 0) act &= (act - 1);
        int i2 = act ? __ffs(act) - 1 : -1;  if (i2 >= 0) act &= (act - 1);
        int i3 = act ? __ffs(act) - 1 : -1;  if (i3 >= 0) act &= (act - 1);
        int j1 = i1 < 0 ? 0 : i1, j2 = i2 < 0 ? 0 : i2, j3 = i3 < 0 ? 0 : i3;
        float w0 = __shfl_sync(0xFFFFFFFFu, w, i0);
        float w1 = __shfl_sync(0xFFFFFFFFu, w, j1);
        float w2 = __shfl_sync(0xFFFFFFFFu, w, j2);
        float w3 = __shfl_sync(0xFFFFFFFFu, w, j3);
        int   s0 = __shfl_sync(0xFFFFFFFFu, segg, i0);
        int   s1 = __shfl_sync(0xFFFFFFFFu, segg, j1);
        int   s2 = __shfl_sync(0xFFFFFFFFu, segg, j2);
        int   s3 = __shfl_sync(0xFFFFFFFFu, segg, j3);
        uint2 v0 = __ldg(&g_xf16[(size_t)(rbase + i0) * 32 + lane]);
        uint2 v1, v2, v3;
        if (i1 >= 0) v1 = __ldg(&g_xf16[(size_t)(rbase + i1) * 32 + lane]);
        if (i2 >= 0) v2 = __ldg(&g_xf16[(size_t)(rbase + i2) * 32 + lane]);
        if (i3 >= 0) v3 = __ldg(&g_xf16[(size_t)(rbase + i3) * 32 + lane]);
        {
            float2 a = __half22float2(*(const __half2*)&v0.x);
            float2 b = __half22float2(*(const __half2*)&v0.y);
            REDV4(out + ((size_t)s0 << 7) + lane * 4, a.x * w0, a.y * w0, b.x * w0, b.y * w0);
        }
        if (i1 >= 0) {
            float2 a = __half22float2(*(const __half2*)&v1.x);
            float2 b = __half22float2(*(const __half2*)&v1.y);
            REDV4(out + ((size_t)s1 << 7) + lane * 4, a.x * w1, a.y * w1, b.x * w1, b.y * w1);
        }
        if (i2 >= 0) {
            float2 a = __half22float2(*(const __half2*)&v2.x);
            float2 b = __half22float2(*(const __half2*)&v2.y);
            REDV4(out + ((size_t)s2 << 7) + lane * 4, a.x * w2, a.y * w2, b.x * w2, b.y * w2);
        }
        if (i3 >= 0) {
            float2 a = __half22float2(*(const __half2*)&v3.x);
            float2 b = __half22float2(*(const __half2*)&v3.y);
            REDV4(out + ((size_t)s3 << 7) + lane * 4, a.x * w3, a.y * w3, b.x * w3, b.y * w3);
        }
    }
}

// ============================ launch ============================
extern "C" void kernel_launch(void* const* d_in, const int* in_sizes, int n_in,
                              void* d_out, int out_size) {
    const float* x     = (const float*)d_in[0];
    const float* W     = (const float*)d_in[1];
    const float* bv    = (const float*)d_in[2];
    const float* ctx   = (const float*)d_in[3];
    const int*   mask  = (const int*)d_in[4];
    const int*   index = (const int*)d_in[5];
    float* out = (float*)d_out;

    cudaFuncSetAttribute(k1_importance, cudaFuncAttributeMaxDynamicSharedMemorySize, SMEM_TOTAL);

    k0_init<<<(OUT_ELEMS + 255) / 256, 256>>>(out, W);
    k1_importance<<<152, 256, SMEM_TOTAL>>>(x, bv, ctx, mask, index);
    k3_scatter<<<(ROWS / 256), 256>>>(index, out);
}

// round 15
// speedup vs baseline: 1.0426x; 1.0347x over previous
#include <cuda_runtime.h>
#include <cuda_fp16.h>
#include <cstdint>

#define BQ    4
#define NSEQ  200000
#define EDIM  128
#define NIDX  2048
#define ROWS  (BQ * NSEQ)            /* 800000 */
#define NTILES (ROWS / 128)          /* 6250 exact */
#define OUT_ELEMS (BQ * NIDX * EDIM) /* 1048576 */
#define ATTN_OFF  OUT_ELEMS
#define NSEG (BQ * NIDX)             /* 8192 */

// ---------------- device scratch (no cudaMalloc allowed) ----------------
__device__ float    g_imp[ROWS];        // exp(importance)  (0 for masked rows)
__device__ float    g_segsum[NSEG];
__device__ uint32_t g_Wfrag[8192];      // W as fragment-ordered fp16x2 pairs (32 KB)
__device__ unsigned g_tilectr;          // work-stealing tile counter

// ---------------- helpers ----------------
__device__ __forceinline__ uint32_t smem_u32(const void* p) {
    uint32_t a;
    asm("{ .reg .u64 t; cvta.to.shared.u64 t, %1; cvt.u32.u64 %0, t; }" : "=r"(a) : "l"(p));
    return a;
}
// pack two f32 -> f16x2 (lo = first arg)
__device__ __forceinline__ uint32_t f16x2_pack(float lo, float hi) {
    uint32_t r;
    asm("cvt.rn.f16x2.f32 %0, %1, %2;" : "=r"(r) : "f"(hi), "f"(lo));
    return r;
}
__device__ __forceinline__ void cp_async16(uint32_t dst, const void* src) {
    asm volatile("cp.async.cg.shared.global [%0], [%1], 16;" :: "r"(dst), "l"(src));
}
#define CP_COMMIT()  asm volatile("cp.async.commit_group;" ::: "memory")
#define CP_WAIT(N)   asm volatile("cp.async.wait_group %0;" :: "n"(N) : "memory")

#define LDS128(r0_, r1_, r2_, r3_, addr) \
    asm volatile("ld.shared.v4.u32 {%0,%1,%2,%3}, [%4];" \
        : "=r"(r0_), "=r"(r1_), "=r"(r2_), "=r"(r3_) : "r"(addr))

#define LDSM_X4(r0_, r1_, r2_, r3_, addr) \
    asm volatile("ldmatrix.sync.aligned.m8n8.x4.shared.b16 {%0,%1,%2,%3}, [%4];" \
        : "=r"(r0_), "=r"(r1_), "=r"(r2_), "=r"(r3_) : "r"(addr))

#define MMA_F16(d, a0, a1, a2, a3, b0, b1) \
    asm volatile("mma.sync.aligned.m16n8k16.row.col.f32.f16.f16.f32 " \
        "{%0,%1,%2,%3}, {%4,%5,%6,%7}, {%8,%9}, {%0,%1,%2,%3};" \
        : "+f"((d)[0]), "+f"((d)[1]), "+f"((d)[2]), "+f"((d)[3]) \
        : "r"(a0), "r"(a1), "r"(a2), "r"(a3), "r"(b0), "r"(b1))

#define REDV4(dst, a, b, c, dd) \
    asm volatile("red.global.add.v4.f32 [%0], {%1, %2, %3, %4};" \
        :: "l"(dst), "f"(a), "f"(b), "f"(c), "f"(dd) : "memory")

// ---------------- SMEM layout (K1) ----------------
// f16 X tile: 128 rows x 136 f16 (272 B stride) -> conflict-free ldmatrix.
// W frags:    [wc(2)][step(8)][lane(32)] x 64B payload padded to 80 B/lane.
#define ROWH_B    272
#define XF16_PB   (128 * ROWH_B)      /* 34816 */
#define SM_B      0                   /* 512B bias (f32)  */
#define SM_CTX    512                 /* 512B ctx  (f32)  */
#define SM_BH     1024                /* 256B bias f16x2 pairs */
#define SM_PACC   1280                /* 1024B            */
#define SM_T      2304                /* 16B tile broadcast */
#define SM_WF     2432                /* 40960B W fragments (16B aligned) */
#define SM_XF16   (SM_WF + 40960)     /* 43392 */
#define SMEM_TOTAL (SM_XF16 + XF16_PB) /* 78208 */

// =========================== K0: init + W fragment pack ===========================
__global__ void k0_init(float* out, const float* __restrict__ W) {
    int i = blockIdx.x * blockDim.x + threadIdx.x;
    if (i < OUT_ELEMS) out[i] = 0.0f;
    if (i < NSEG) g_segsum[i] = 0.0f;
    if (i < 8192) {
        int h  = i & 1;          // k-half (+8)
        int nb = (i >> 1) & 7;   // n8 block within warp's 64 cols
        int ln = (i >> 4) & 31;  // lane
        int st = (i >> 9) & 7;   // k16 step
        int wc = i >> 12;        // warp_c
        int r0 = ln >> 2, c0 = ln & 3;
        int n = 64 * wc + 8 * nb + r0;
        int k = 16 * st + 2 * c0 + 8 * h;
        uint32_t p = f16x2_pack(W[n * 128 + k], W[n * 128 + k + 1]);
        g_Wfrag[((wc * 8 + st) * 32 + ln) * 16 + nb * 2 + h] = p;
    }
    if (i == 0) g_tilectr = 0u;
}

// ============ K1: persistent fp16 GEMM + f16x2 tanh + exp + segsum ============
// No max-subtraction: importance is bounded (|imp| <= ~9); masked rows -> exp(-1e9) == 0.
__global__ __launch_bounds__(256, 1)
void k1_importance(const float* __restrict__ x,
                   const float* __restrict__ bv, const float* __restrict__ ctx,
                   const int* __restrict__ mask, const int* __restrict__ index) {
    extern __shared__ char smem[];
    uint32_t sbase = smem_u32(smem);
    int tid = threadIdx.x;
    int l = tid & 31, wid = tid >> 5;
    int warp_r = wid & 3;        // rows 32*warp_r .. +31
    int warp_c = wid >> 2;       // cols 64*warp_c .. +63
    int r0 = l >> 2, c0 = l & 3;
    int* smt = (int*)(smem + SM_T);

    if (tid < 128) {
        ((float*)(smem + SM_B))[tid]   = bv[tid];
        ((float*)(smem + SM_CTX))[tid] = ctx[tid];
    }
    if (tid < 64)
        ((uint32_t*)(smem + SM_BH))[tid] = f16x2_pack(bv[2 * tid], bv[2 * tid + 1]);
    if (tid == 0) smt[0] = (int)atomicAdd(&g_tilectr, 1u);
    __syncthreads();
    int t = smt[0];
    if (t >= NTILES) return;     // late CTA under work stealing (uniform per CTA)

    // copy W fragments into padded smem (2048 x 16B)
#pragma unroll
    for (int i = 0; i < 8; i++) {
        int c = i * 256 + tid;
        int grp = c >> 2, off = c & 3;
        cp_async16(sbase + SM_WF + grp * 80 + off * 16, (const char*)g_Wfrag + c * 16);
    }
    CP_COMMIT();

    // prefetch first x tile into registers
    const float4* xb = (const float4*)x;
    float4 xr[16];
#pragma unroll
    for (int i = 0; i < 16; i++)
        xr[i] = __ldg(xb + (size_t)t * 4096 + i * 256 + tid);

    CP_WAIT(0);   // own W chunks done; cross-thread visibility via in-loop sync

    // per-lane bases
    const uint32_t a_sm = sbase + SM_XF16
                        + (uint32_t)(32 * warp_r + (l & 15)) * ROWH_B + ((l >> 4) << 4);
    const uint32_t wf_base = sbase + SM_WF + (uint32_t)((warp_c * 8) * 32 + l) * 80;
    const float* sc = (const float*)(smem + SM_CTX);
    const uint32_t* sbh = (const uint32_t*)(smem + SM_BH);
    float* pacc = (float*)(smem + SM_PACC);
    char* Hp = smem + SM_XF16;

    for (;;) {
        // ---- convert + store current tile's x (from regs) into shared f16 ----
#pragma unroll
        for (int i = 0; i < 16; i++) {
            int c = i * 256 + tid;
            int row = c >> 5, u = c & 31;
            uint2 p;
            p.x = f16x2_pack(xr[i].x, xr[i].y);
            p.y = f16x2_pack(xr[i].z, xr[i].w);
            *(uint2*)(Hp + row * ROWH_B + u * 8) = p;
        }
        if (tid == 0) smt[0] = (int)atomicAdd(&g_tilectr, 1u);
        __syncthreads();                       // STS visible; smt visible; W visible (1st iter)
        int tn = smt[0];
        bool pend = (tn < NTILES);
        if (pend) {                            // prefetch next tile; hidden under MMA loop
#pragma unroll
            for (int i = 0; i < 16; i++)
                xr[i] = __ldg(xb + (size_t)tn * 4096 + i * 256 + tid);
        }

        float d[2][8][4];
#pragma unroll
        for (int mb = 0; mb < 2; mb++)
#pragma unroll
            for (int nb = 0; nb < 8; nb++)
#pragma unroll
                for (int r = 0; r < 4; r++) d[mb][nb][r] = 0.0f;

#pragma unroll
        for (int st = 0; st < 8; st++) {       // 8 k16 steps (32B each along row)
            uint32_t A[2][4];
            LDSM_X4(A[0][0], A[0][1], A[0][2], A[0][3], a_sm + st * 32);
            LDSM_X4(A[1][0], A[1][1], A[1][2], A[1][3], a_sm + st * 32 + 16 * ROWH_B);
            uint32_t Bv[4][4];
            uint32_t ba = wf_base + (uint32_t)(st * 32) * 80;
#pragma unroll
            for (int q = 0; q < 4; q++)
                LDS128(Bv[q][0], Bv[q][1], Bv[q][2], Bv[q][3], ba + q * 16);
#pragma unroll
            for (int nb = 0; nb < 8; nb++) {
                uint32_t bb0 = Bv[nb >> 1][(nb & 1) * 2];
                uint32_t bb1 = Bv[nb >> 1][(nb & 1) * 2 + 1];
                MMA_F16(d[0][nb], A[0][0], A[0][1], A[0][2], A[0][3], bb0, bb1);
                MMA_F16(d[1][nb], A[1][0], A[1][1], A[1][2], A[1][3], bb0, bb1);
            }
        }

        // ---- epilogue: f16x2 tanh.approx + f32 ctx-dot on fragments ----
        // frag: reg0:(r,c) reg1:(r,c+1) reg2:(r+8,c) reg3:(r+8,c+1); c even.
        float acc[4] = {0.f, 0.f, 0.f, 0.f};   // [mb*2 + hi8]
#pragma unroll
        for (int mb = 0; mb < 2; mb++) {
#pragma unroll
            for (int nb = 0; nb < 8; nb++) {
                int cb = 64 * warp_c + nb * 8 + c0 * 2;
                uint32_t bh = sbh[cb >> 1];
                uint32_t p01 = f16x2_pack(d[mb][nb][0], d[mb][nb][1]);
                uint32_t p23 = f16x2_pack(d[mb][nb][2], d[mb][nb][3]);
                asm("add.rn.f16x2 %0, %1, %2;" : "=r"(p01) : "r"(p01), "r"(bh));
                asm("add.rn.f16x2 %0, %1, %2;" : "=r"(p23) : "r"(p23), "r"(bh));
                asm("tanh.approx.f16x2 %0, %1;" : "=r"(p01) : "r"(p01));
                asm("tanh.approx.f16x2 %0, %1;" : "=r"(p23) : "r"(p23));
                float2 f01 = __half22float2(*(const __half2*)&p01);
                float2 f23 = __half22float2(*(const __half2*)&p23);
                float cx0 = sc[cb], cx1 = sc[cb + 1];
                acc[mb * 2 + 0] = fmaf(cx0, f01.x, fmaf(cx1, f01.y, acc[mb * 2 + 0]));
                acc[mb * 2 + 1] = fmaf(cx0, f23.x, fmaf(cx1, f23.y, acc[mb * 2 + 1]));
            }
        }
#pragma unroll
        for (int s = 0; s < 4; s++) {
            acc[s] += __shfl_xor_sync(0xFFFFFFFFu, acc[s], 1);
            acc[s] += __shfl_xor_sync(0xFFFFFFFFu, acc[s], 2);
        }
        if (c0 == 0) {
#pragma unroll
            for (int s = 0; s < 4; s++) {
                int row = 32 * warp_r + 16 * (s >> 1) + 8 * (s & 1) + r0;
                pacc[row * 2 + warp_c] = acc[s];
            }
        }
        __syncthreads();   // pacc ready; also: all Xf16 reads done before next STS

        if (tid < 128) {
            float impv = (pacc[tid * 2] + pacc[tid * 2 + 1]) * 0.08838834764831843f;
            int row = t * 128 + tid;
            float e = 0.0f;
            if (mask[row] != 0) {
                e = __expf(impv);              // |impv| <= ~9: no overflow possible
                int seg = index[row];
                int bq = row / NSEQ;
                atomicAdd(&g_segsum[bq * NIDX + seg], e);
            }
            g_imp[row] = e;
        }

        if (!pend) break;
        t = tn;
    }
}

// ============ K3: weights + scatter-add of x (32 rows/warp, 4-way unrolled) ============
__global__ __launch_bounds__(256)
void k3_scatter(const float* __restrict__ x, const int* __restrict__ index,
                float* __restrict__ out) {
    int warp = (blockIdx.x << 3) + (threadIdx.x >> 5);   // 25000 warps
    int lane = threadIdx.x & 31;
    int rbase = warp * 32;                               // NSEQ % 32 == 0: no bq straddle
    int row = rbase + lane;

    float e  = g_imp[row];
    int seg  = index[row];
    int bq   = row / NSEQ;
    int segg = bq * NIDX + seg;
    float s  = g_segsum[segg];
    float w  = (e != 0.0f) ? e / s : 0.0f;
    out[ATTN_OFF + row] = w;

    const float4* xb = (const float4*)x;
    unsigned act = __ballot_sync(0xFFFFFFFFu, w != 0.0f);
    while (act) {
        int i0 = __ffs(act) - 1;             act &= (act - 1);
        int i1 = act ? __ffs(act) - 1 : -1;  if (i1 >= 0) act &= (act - 1);
        int i2 = act ? __ffs(act) - 1 : -1;  if (i2 >= 0) act &= (act - 1);
        int i3 = act ? __ffs(act) - 1 : -1;  if (i3 >= 0) act &= (act - 1);
        int j1 = i1 < 0 ? 0 : i1, j2 = i2 < 0 ? 0 : i2, j3 = i3 < 0 ? 0 : i3;
        float w0 = __shfl_sync(0xFFFFFFFFu, w, i0);
        float w1 = __shfl_sync(0xFFFFFFFFu, w, j1);
        float w2 = __shfl_sync(0xFFFFFFFFu, w, j2);
        float w3 = __shfl_sync(0xFFFFFFFFu, w, j3);
        int   s0 = __shfl_sync(0xFFFFFFFFu, segg, i0);
        int   s1 = __shfl_sync(0xFFFFFFFFu, segg, j1);
        int   s2 = __shfl_sync(0xFFFFFFFFu, segg, j2);
        int   s3 = __shfl_sync(0xFFFFFFFFu, segg, j3);
        float4 v0 = __ldg(xb + (size_t)(rbase + i0) * 32 + lane);
        float4 v1, v2, v3;
        if (i1 >= 0) v1 = __ldg(xb + (size_t)(rbase + i1) * 32 + lane);
        if (i2 >= 0) v2 = __ldg(xb + (size_t)(rbase + i2) * 32 + lane);
        if (i3 >= 0) v3 = __ldg(xb + (size_t)(rbase + i3) * 32 + lane);
        REDV4(out + ((size_t)s0 << 7) + lane * 4, v0.x * w0, v0.y * w0, v0.z * w0, v0.w * w0);
        if (i1 >= 0)
            REDV4(out + ((size_t)s1 << 7) + lane * 4, v1.x * w1, v1.y * w1, v1.z * w1, v1.w * w1);
        if (i2 >= 0)
            REDV4(out + ((size_t)s2 << 7) + lane * 4, v2.x * w2, v2.y * w2, v2.z * w2, v2.w * w2);
        if (i3 >= 0)
            REDV4(out + ((size_t)s3 << 7) + lane * 4, v3.x * w3, v3.y * w3, v3.z * w3, v3.w * w3);
    }
}

// ============================ launch ============================
extern "C" void kernel_launch(void* const* d_in, const int* in_sizes, int n_in,
                              void* d_out, int out_size) {
    const float* x     = (const float*)d_in[0];
    const float* W     = (const float*)d_in[1];
    const float* bv    = (const float*)d_in[2];
    const float* ctx   = (const float*)d_in[3];
    const int*   mask  = (const int*)d_in[4];
    const int*   index = (const int*)d_in[5];
    float* out = (float*)d_out;

    cudaFuncSetAttribute(k1_importance, cudaFuncAttributeMaxDynamicSharedMemorySize, SMEM_TOTAL);

    k0_init<<<(OUT_ELEMS + 255) / 256, 256>>>(out, W);
    k1_importance<<<152, 256, SMEM_TOTAL>>>(x, bv, ctx, mask, index);
    k3_scatter<<<(ROWS / 256), 256>>>(x, index, out);
}

// round 16
// speedup vs baseline: 1.2524x; 1.2012x over previous
#include <cuda_runtime.h>
#include <cuda_fp16.h>
#include <cstdint>

#define BQ    4
#define NSEQ  200000
#define EDIM  128
#define NIDX  2048
#define ROWS  (BQ * NSEQ)            /* 800000 */
#define NTILES (ROWS / 128)          /* 6250 exact */
#define OUT_ELEMS (BQ * NIDX * EDIM) /* 1048576 */
#define ATTN_OFF  OUT_ELEMS
#define NSEG (BQ * NIDX)             /* 8192 */

// ---------------- device scratch (no cudaMalloc allowed) ----------------
__device__ float    g_imp[ROWS];        // exp(importance)  (0 for masked rows)
__device__ float    g_segsum[NSEG];
__device__ uint32_t g_Wfrag[8192];      // W as fragment-ordered fp16x2 pairs (32 KB)
__device__ unsigned g_tilectr;          // work-stealing tile counter

// ---------------- helpers ----------------
__device__ __forceinline__ uint32_t smem_u32(const void* p) {
    uint32_t a;
    asm("{ .reg .u64 t; cvta.to.shared.u64 t, %1; cvt.u32.u64 %0, t; }" : "=r"(a) : "l"(p));
    return a;
}
// pack two f32 -> f16x2 (lo = first arg)
__device__ __forceinline__ uint32_t f16x2_pack(float lo, float hi) {
    uint32_t r;
    asm("cvt.rn.f16x2.f32 %0, %1, %2;" : "=r"(r) : "f"(hi), "f"(lo));
    return r;
}
__device__ __forceinline__ float tanh_approx(float f) {
    float r;
    asm("tanh.approx.f32 %0, %1;" : "=f"(r) : "f"(f));
    return r;
}
__device__ __forceinline__ void cp_async16(uint32_t dst, const void* src) {
    asm volatile("cp.async.cg.shared.global [%0], [%1], 16;" :: "r"(dst), "l"(src));
}
#define CP_COMMIT()  asm volatile("cp.async.commit_group;" ::: "memory")
#define CP_WAIT(N)   asm volatile("cp.async.wait_group %0;" :: "n"(N) : "memory")

#define LDS128(r0_, r1_, r2_, r3_, addr) \
    asm volatile("ld.shared.v4.u32 {%0,%1,%2,%3}, [%4];" \
        : "=r"(r0_), "=r"(r1_), "=r"(r2_), "=r"(r3_) : "r"(addr))

#define LDSM_X4(r0_, r1_, r2_, r3_, addr) \
    asm volatile("ldmatrix.sync.aligned.m8n8.x4.shared.b16 {%0,%1,%2,%3}, [%4];" \
        : "=r"(r0_), "=r"(r1_), "=r"(r2_), "=r"(r3_) : "r"(addr))

#define MMA_F16(d, a0, a1, a2, a3, b0, b1) \
    asm volatile("mma.sync.aligned.m16n8k16.row.col.f32.f16.f16.f32 " \
        "{%0,%1,%2,%3}, {%4,%5,%6,%7}, {%8,%9}, {%0,%1,%2,%3};" \
        : "+f"((d)[0]), "+f"((d)[1]), "+f"((d)[2]), "+f"((d)[3]) \
        : "r"(a0), "r"(a1), "r"(a2), "r"(a3), "r"(b0), "r"(b1))

#define REDV4(dst, a, b, c, dd) \
    asm volatile("red.global.add.v4.f32 [%0], {%1, %2, %3, %4};" \
        :: "l"(dst), "f"(a), "f"(b), "f"(c), "f"(dd) : "memory")

// ---------------- SMEM layout (K1) ----------------
// f16 X tile: 128 rows x 136 f16 (272 B stride) -> conflict-free ldmatrix.
// W frags:    [wc(2)][step(8)][lane(32)] x 64B payload padded to 80 B/lane.
#define ROWH_B    272
#define XF16_PB   (128 * ROWH_B)      /* 34816 */
#define SM_B      0                   /* 512B bias   */
#define SM_CTX    512                 /* 512B ctx    */
#define SM_PACC   1024                /* 1024B       */
#define SM_T      2048                /* 16B tile broadcast */
#define SM_WF     2176                /* 40960B W fragments */
#define SM_XF16   (SM_WF + 40960)     /* 43136 */
#define SMEM_TOTAL (SM_XF16 + XF16_PB) /* 77952: 2 CTAs/SM = 156 KB < 227 KB */

// =========================== K0: init + W fragment pack ===========================
__global__ void k0_init(float* out, const float* __restrict__ W) {
    int i = blockIdx.x * blockDim.x + threadIdx.x;
    if (i < OUT_ELEMS) out[i] = 0.0f;
    if (i < NSEG) g_segsum[i] = 0.0f;
    if (i < 8192) {
        int h  = i & 1;          // k-half (+8)
        int nb = (i >> 1) & 7;   // n8 block within warp's 64 cols
        int ln = (i >> 4) & 31;  // lane
        int st = (i >> 9) & 7;   // k16 step
        int wc = i >> 12;        // warp_c
        int r0 = ln >> 2, c0 = ln & 3;
        int n = 64 * wc + 8 * nb + r0;
        int k = 16 * st + 2 * c0 + 8 * h;
        uint32_t p = f16x2_pack(W[n * 128 + k], W[n * 128 + k + 1]);
        g_Wfrag[((wc * 8 + st) * 32 + ln) * 16 + nb * 2 + h] = p;
    }
    if (i == 0) g_tilectr = 0u;
}

// ============ K1: persistent fp16 GEMM + tanh + exp + segsum, 2 CTAs/SM ============
// x is converted f32->f16x2 at LOAD time (prefetch shadow), so the per-tile
// critical path between barriers is STS-only; regs fit the 128 cap for occupancy 2.
__global__ __launch_bounds__(256, 2)
void k1_importance(const float* __restrict__ x,
                   const float* __restrict__ bv, const float* __restrict__ ctx,
                   const int* __restrict__ mask, const int* __restrict__ index) {
    extern __shared__ char smem[];
    uint32_t sbase = smem_u32(smem);
    int tid = threadIdx.x;
    int l = tid & 31, wid = tid >> 5;
    int warp_r = wid & 3;        // rows 32*warp_r .. +31
    int warp_c = wid >> 2;       // cols 64*warp_c .. +63
    int r0 = l >> 2, c0 = l & 3;
    int* smt = (int*)(smem + SM_T);

    if (tid < 128) {
        ((float*)(smem + SM_B))[tid]   = bv[tid];
        ((float*)(smem + SM_CTX))[tid] = ctx[tid];
    }
    if (tid == 0) smt[0] = (int)atomicAdd(&g_tilectr, 1u);
    __syncthreads();
    int t = smt[0];
    if (t >= NTILES) return;     // late CTA under work stealing (uniform per CTA)

    // copy W fragments into padded smem (2048 x 16B)
#pragma unroll
    for (int i = 0; i < 8; i++) {
        int c = i * 256 + tid;
        int grp = c >> 2, off = c & 3;
        cp_async16(sbase + SM_WF + grp * 80 + off * 16, (const char*)g_Wfrag + c * 16);
    }
    CP_COMMIT();

    // prefetch first x tile: LDG.128 + convert to packed f16x2 (32 regs, not 64)
    const float4* xb = (const float4*)x;
    uint2 xr[16];
#pragma unroll
    for (int i = 0; i < 16; i++) {
        float4 v = __ldg(xb + (size_t)t * 4096 + i * 256 + tid);
        xr[i].x = f16x2_pack(v.x, v.y);
        xr[i].y = f16x2_pack(v.z, v.w);
    }

    CP_WAIT(0);   // own W chunks done; cross-thread visibility via in-loop sync

    // per-lane bases
    const uint32_t a_sm = sbase + SM_XF16
                        + (uint32_t)(32 * warp_r + (l & 15)) * ROWH_B + ((l >> 4) << 4);
    const uint32_t wf_base = sbase + SM_WF + (uint32_t)((warp_c * 8) * 32 + l) * 80;
    const float* sb = (const float*)(smem + SM_B);
    const float* sc = (const float*)(smem + SM_CTX);
    float* pacc = (float*)(smem + SM_PACC);
    char* Hp = smem + SM_XF16;

    for (;;) {
        // ---- store current tile's packed x into shared f16 (STS only) ----
#pragma unroll
        for (int i = 0; i < 16; i++) {
            int c = i * 256 + tid;
            int row = c >> 5, u = c & 31;
            *(uint2*)(Hp + row * ROWH_B + u * 8) = xr[i];
        }
        if (tid == 0) smt[0] = (int)atomicAdd(&g_tilectr, 1u);
        __syncthreads();                       // STS visible; smt visible; W visible (1st iter)
        int tn = smt[0];
        bool pend = (tn < NTILES);
        if (pend) {                            // prefetch+convert next tile under MMA loop
#pragma unroll
            for (int i = 0; i < 16; i++) {
                float4 v = __ldg(xb + (size_t)tn * 4096 + i * 256 + tid);
                xr[i].x = f16x2_pack(v.x, v.y);
                xr[i].y = f16x2_pack(v.z, v.w);
            }
        }

        float d[2][8][4];
#pragma unroll
        for (int mb = 0; mb < 2; mb++)
#pragma unroll
            for (int nb = 0; nb < 8; nb++)
#pragma unroll
                for (int r = 0; r < 4; r++) d[mb][nb][r] = 0.0f;

#pragma unroll
        for (int st = 0; st < 8; st++) {       // 8 k16 steps (32B each along row)
            uint32_t A[2][4];
            LDSM_X4(A[0][0], A[0][1], A[0][2], A[0][3], a_sm + st * 32);
            LDSM_X4(A[1][0], A[1][1], A[1][2], A[1][3], a_sm + st * 32 + 16 * ROWH_B);
            uint32_t Bv[4][4];
            uint32_t ba = wf_base + (uint32_t)(st * 32) * 80;
#pragma unroll
            for (int q = 0; q < 4; q++)
                LDS128(Bv[q][0], Bv[q][1], Bv[q][2], Bv[q][3], ba + q * 16);
#pragma unroll
            for (int nb = 0; nb < 8; nb++) {
                uint32_t bb0 = Bv[nb >> 1][(nb & 1) * 2];
                uint32_t bb1 = Bv[nb >> 1][(nb & 1) * 2 + 1];
                MMA_F16(d[0][nb], A[0][0], A[0][1], A[0][2], A[0][3], bb0, bb1);
                MMA_F16(d[1][nb], A[1][0], A[1][1], A[1][2], A[1][3], bb0, bb1);
            }
        }

        // ---- epilogue: tanh.approx + ctx-dot on fragments ----
        float acc[4] = {0.f, 0.f, 0.f, 0.f};   // [mb*2 + hi8]
#pragma unroll
        for (int mb = 0; mb < 2; mb++) {
#pragma unroll
            for (int nb = 0; nb < 8; nb++) {
                int cb = 64 * warp_c + nb * 8 + c0 * 2;
#pragma unroll
                for (int r = 0; r < 4; r++) {
                    int c = cb + (r & 1);
                    float th = tanh_approx(d[mb][nb][r] + sb[c]);
                    acc[mb * 2 + (r >> 1)] = fmaf(sc[c], th, acc[mb * 2 + (r >> 1)]);
                }
            }
        }
#pragma unroll
        for (int s = 0; s < 4; s++) {
            acc[s] += __shfl_xor_sync(0xFFFFFFFFu, acc[s], 1);
            acc[s] += __shfl_xor_sync(0xFFFFFFFFu, acc[s], 2);
        }
        if (c0 == 0) {
#pragma unroll
            for (int s = 0; s < 4; s++) {
                int row = 32 * warp_r + 16 * (s >> 1) + 8 * (s & 1) + r0;
                pacc[row * 2 + warp_c] = acc[s];
            }
        }
        __syncthreads();   // pacc ready; also: all Xf16 reads done before next STS

        if (tid < 128) {
            float impv = (pacc[tid * 2] + pacc[tid * 2 + 1]) * 0.08838834764831843f;
            int row = t * 128 + tid;
            float e = 0.0f;
            if (mask[row] != 0) {
                e = __expf(impv);              // |impv| <= ~9: no overflow possible
                int seg = index[row];
                int bq = row / NSEQ;
                atomicAdd(&g_segsum[bq * NIDX + seg], e);
            }
            g_imp[row] = e;
        }

        if (!pend) break;
        t = tn;
    }
}

// ============ K3: weights + scatter-add of x (32 rows/warp, 4-way unrolled) ============
__global__ __launch_bounds__(256)
void k3_scatter(const float* __restrict__ x, const int* __restrict__ index,
                float* __restrict__ out) {
    int warp = (blockIdx.x << 3) + (threadIdx.x >> 5);   // 25000 warps
    int lane = threadIdx.x & 31;
    int rbase = warp * 32;                               // NSEQ % 32 == 0: no bq straddle
    int row = rbase + lane;

    float e  = g_imp[row];
    int seg  = index[row];
    int bq   = row / NSEQ;
    int segg = bq * NIDX + seg;
    float s  = g_segsum[segg];
    float w  = (e != 0.0f) ? e / s : 0.0f;
    out[ATTN_OFF + row] = w;

    const float4* xb = (const float4*)x;
    unsigned act = __ballot_sync(0xFFFFFFFFu, w != 0.0f);
    while (act) {
        int i0 = __ffs(act) - 1;             act &= (act - 1);
        int i1 = act ? __ffs(act) - 1 : -1;  if (i1 >= 0) act &= (act - 1);
        int i2 = act ? __ffs(act) - 1 : -1;  if (i2 >= 0) act &= (act - 1);
        int i3 = act ? __ffs(act) - 1 : -1;  if (i3 >= 0) act &= (act - 1);
        int j1 = i1 < 0 ? 0 : i1, j2 = i2 < 0 ? 0 : i2, j3 = i3 < 0 ? 0 : i3;
        float w0 = __shfl_sync(0xFFFFFFFFu, w, i0);
        float w1 = __shfl_sync(0xFFFFFFFFu, w, j1);
        float w2 = __shfl_sync(0xFFFFFFFFu, w, j2);
        float w3 = __shfl_sync(0xFFFFFFFFu, w, j3);
        int   s0 = __shfl_sync(0xFFFFFFFFu, segg, i0);
        int   s1 = __shfl_sync(0xFFFFFFFFu, segg, j1);
        int   s2 = __shfl_sync(0xFFFFFFFFu, segg, j2);
        int   s3 = __shfl_sync(0xFFFFFFFFu, segg, j3);
        float4 v0 = __ldg(xb + (size_t)(rbase + i0) * 32 + lane);
        float4 v1, v2, v3;
        if (i1 >= 0) v1 = __ldg(xb + (size_t)(rbase + i1) * 32 + lane);
        if (i2 >= 0) v2 = __ldg(xb + (size_t)(rbase + i2) * 32 + lane);
        if (i3 >= 0) v3 = __ldg(xb + (size_t)(rbase + i3) * 32 + lane);
        REDV4(out + ((size_t)s0 << 7) + lane * 4, v0.x * w0, v0.y * w0, v0.z * w0, v0.w * w0);
        if (i1 >= 0)
            REDV4(out + ((size_t)s1 << 7) + lane * 4, v1.x * w1, v1.y * w1, v1.z * w1, v1.w * w1);
        if (i2 >= 0)
            REDV4(out + ((size_t)s2 << 7) + lane * 4, v2.x * w2, v2.y * w2, v2.z * w2, v2.w * w2);
        if (i3 >= 0)
            REDV4(out + ((size_t)s3 << 7) + lane * 4, v3.x * w3, v3.y * w3, v3.z * w3, v3.w * w3);
    }
}

// ============================ launch ============================
extern "C" void kernel_launch(void* const* d_in, const int* in_sizes, int n_in,
                              void* d_out, int out_size) {
    const float* x     = (const float*)d_in[0];
    const float* W     = (const float*)d_in[1];
    const float* bv    = (const float*)d_in[2];
    const float* ctx   = (const float*)d_in[3];
    const int*   mask  = (const int*)d_in[4];
    const int*   index = (const int*)d_in[5];
    float* out = (float*)d_out;

    cudaFuncSetAttribute(k1_importance, cudaFuncAttributeMaxDynamicSharedMemorySize, SMEM_TOTAL);

    k0_init<<<(OUT_ELEMS + 255) / 256, 256>>>(out, W);
    k1_importance<<<304, 256, SMEM_TOTAL>>>(x, bv, ctx, mask, index);
    k3_scatter<<<(ROWS / 256), 256>>>(x, index, out);
}